// round 4
// baseline (speedup 1.0000x reference)
#include <cuda_runtime.h>
#include <cuda_fp16.h>

#define BB   256
#define NN   1152
#define OO   10
#define JJ   160              // OO * 16 floats per (b,n)
#define WW   80               // half2 words per (b,n); w = o*8 + q (q = k-pair)
#define EPSF 1e-7f
#define NPART 8
#define NPERW 18              // 1152 / (NPART*8 warps)

// ---- scratch (static device globals; no allocation) ----
__device__ __half2 g_uh[(size_t)BB * NN * WW];     // 94.5 MB, [b][n][w]
__device__ float   g_s0[BB * JJ];
__device__ float   g_sA[BB * JJ];
__device__ float   g_sB[BB * JJ];
__device__ float   g_v[BB * JJ];
__device__ float   g_b1[(size_t)BB * NN * OO];     // 11.8 MB logits after iter-0

// ---------------------------------------------------------------------------
__global__ void k_zero() {
    int i = blockIdx.x * blockDim.x + threadIdx.x;
    if (i < BB * JJ) { g_s0[i] = 0.f; g_sA[i] = 0.f; g_sB[i] = 0.f; }
}

// ---------------------------------------------------------------------------
// u_hat (fp32 compute, fp16 store) + iter-0 sums via direct atomics.
// grid (36, 8): 32 n per block (4 chunks of 8), 32 b per block.  block 160 (j).
__global__ void __launch_bounds__(160) k_uhat(const float* __restrict__ x,
                                              const float* __restrict__ w) {
    const int j  = threadIdx.x;
    const int n0 = blockIdx.x * 32;
    const int b0 = blockIdx.y * 32;

    __shared__ __align__(16) float x_sm[32 * 64];     // [bb][local n*8+i]
    __shared__ float acc_sm[32][JJ];                  // s0 partials per bb

    for (int bb = j; bb < 32 * JJ; bb += 160) ((float*)acc_sm)[bb] = 0.f;

    __half* gh = (__half*)g_uh;
    const int wb = (j >> 4) * 128 + (j & 15);         // o*128 + k

    for (int c = 0; c < 4; c++) {
        const int n0c = n0 + c * 8;
        __syncthreads();                              // protect x_sm reuse
        for (int idx = j; idx < 32 * 64; idx += 160) {
            int bb = idx >> 6, q = idx & 63;
            x_sm[idx] = x[(size_t)(b0 + bb) * (NN * 8) + n0c * 8 + q];
        }
        float Wr[8][8];
        #pragma unroll
        for (int n = 0; n < 8; n++)
            #pragma unroll
            for (int i = 0; i < 8; i++)
                Wr[n][i] = w[(size_t)(n0c + n) * 1280 + wb + i * 16];
        __syncthreads();

        for (int bb = 0; bb < 32; bb++) {
            float acc = 0.f;
            __half* outp = &gh[((size_t)(b0 + bb) * NN + n0c) * JJ + j];
            #pragma unroll
            for (int n = 0; n < 8; n++) {
                const float4* xv = reinterpret_cast<const float4*>(&x_sm[bb * 64 + n * 8]);
                float4 xa = xv[0], xb = xv[1];
                float u = Wr[n][0] * xa.x + Wr[n][1] * xa.y + Wr[n][2] * xa.z + Wr[n][3] * xa.w
                        + Wr[n][4] * xb.x + Wr[n][5] * xb.y + Wr[n][6] * xb.z + Wr[n][7] * xb.w;
                outp[n * JJ] = __float2half(u);
                acc += u;
            }
            acc_sm[bb][j] += acc;
        }
    }
    __syncthreads();
    for (int bb = 0; bb < 32; bb++)
        if (j < JJ) {}                                 // (no-op; j always < JJ)
    for (int bb = 0; bb < 32; bb++)
        ;                                              // keep structure simple below
    for (int bb = 0; bb < 32; bb++) {
        // one atomic per (b,j) per block: 36 adders per target element
        if (bb == 0 || true) {}
    }
    for (int bb = 0; bb < 32; bb++)
        atomicAdd(&g_s0[(b0 + bb) * JJ + j], acc_sm[bb][j]);
}

// ---------------------------------------------------------------------------
// squash: dst = squash(scale*s + bias).  grid 256, block 160.
__global__ void k_squash(const float* __restrict__ sbuf, float scale,
                         const float* __restrict__ bias, float* __restrict__ dst) {
    const int b = blockIdx.x, j = threadIdx.x;
    float s = scale * sbuf[b * JJ + j] + bias[j];
    float d = s * s;
    #pragma unroll
    for (int msk = 1; msk < 16; msk <<= 1)
        d += __shfl_xor_sync(0xffffffffu, d, msk, 16);
    dst[b * JJ + j] = s * (d / ((1.f + d) * sqrtf(d + EPSF)));
}

// ---------------------------------------------------------------------------
// Routing iteration.  grid (256 b, NPART), block 256 (8 warps, NPERW n each).
// Lanes 0..19 each own 16B of the 320B u-row: lane l -> half2 words 4l..4l+3,
// o = l>>1 (even lane: k 0-7, odd lane: k 8-15).
template <int LAST>
__global__ void __launch_bounds__(256) k_route(float* __restrict__ sbuf) {
    const int b   = blockIdx.x;
    const int tid = threadIdx.x;
    const int wp  = tid >> 5, l = tid & 31;
    const unsigned FULL = 0xffffffffu;
    const bool act = (l < 20);

    float4 va = make_float4(0.f, 0.f, 0.f, 0.f), vb = va;
    if (act) {
        const float4* vp = (const float4*)(g_v + b * JJ);
        va = vp[2 * l]; vb = vp[2 * l + 1];
    }
    float4 sa = make_float4(0.f, 0.f, 0.f, 0.f), sb = sa;

    const __half2* up = g_uh + (size_t)b * NN * WW;
    const int nbeg = (blockIdx.y * 8 + wp) * NPERW;

    #pragma unroll 3
    for (int nn = 0; nn < NPERW; nn++) {
        const int n = nbeg + nn;
        float4 uw = make_float4(0.f, 0.f, 0.f, 0.f);
        if (act) uw = ((const float4*)(up + (size_t)n * WW))[l];
        const __half2* hp = (const __half2*)&uw;
        float2 u0 = __half22float2(hp[0]), u1 = __half22float2(hp[1]);
        float2 u2 = __half22float2(hp[2]), u3 = __half22float2(hp[3]);

        float p = u0.x * va.x + u0.y * va.y + u1.x * va.z + u1.y * va.w
                + u2.x * vb.x + u2.y * vb.y + u3.x * vb.z + u3.y * vb.w;
        p += __shfl_xor_sync(FULL, p, 1);                 // full o-dot on lane pair
        float dsel = __shfl_sync(FULL, p, (l & 15) << 1); // lanes 0..9: dot[o=l]

        float bn = dsel;
        if (LAST) {
            if (l < 10) bn += g_b1[((size_t)b * NN + n) * OO + l];
        } else {
            if (l < 10) g_b1[((size_t)b * NN + n) * OO + l] = bn;
        }
        float e = (l < 10) ? __expf(bn) : 0.f;
        float tot = e;
        #pragma unroll
        for (int msk = 1; msk < 16; msk <<= 1)
            tot += __shfl_xor_sync(FULL, tot, msk, 16);
        float cn = __fdividef(e, tot);                    // valid on lanes 0..15
        float c = __shfl_sync(FULL, cn, l >> 1);          // c[o] to lane pair

        sa.x += c * u0.x; sa.y += c * u0.y; sa.z += c * u1.x; sa.w += c * u1.y;
        sb.x += c * u2.x; sb.y += c * u2.y; sb.z += c * u3.x; sb.w += c * u3.y;
    }

    __shared__ float ssm[8][JJ];
    if (act) {
        float4* sp = (float4*)&ssm[wp][8 * l];
        sp[0] = sa; sp[1] = sb;
    }
    __syncthreads();

    if (tid < JJ) {
        float s = 0.f;
        #pragma unroll
        for (int w8 = 0; w8 < 8; w8++) s += ssm[w8][tid];
        atomicAdd(&sbuf[b * JJ + tid], s);
    }
}

// ---------------------------------------------------------------------------
extern "C" void kernel_launch(void* const* d_in, const int* in_sizes, int n_in,
                              void* d_out, int out_size) {
    const float* x    = (const float*)d_in[0];
    const float* w    = (const float*)d_in[1];
    const float* bias = (const float*)d_in[2];
    float* out = (float*)d_out;

    float* s0; cudaGetSymbolAddress((void**)&s0, g_s0);
    float* sA; cudaGetSymbolAddress((void**)&sA, g_sA);
    float* sB; cudaGetSymbolAddress((void**)&sB, g_sB);
    float* v;  cudaGetSymbolAddress((void**)&v,  g_v);

    k_zero<<<40, 1024>>>();
    k_uhat<<<dim3(36, 8), 160>>>(x, w);
    k_squash<<<256, 160>>>(s0, 0.1f, bias, v);        // v0
    k_route<0><<<dim3(256, NPART), 256>>>(sA);        // iter 1 + b1
    k_squash<<<256, 160>>>(sA, 1.0f, bias, v);        // v1
    k_route<1><<<dim3(256, NPART), 256>>>(sB);        // iter 2
    k_squash<<<256, 160>>>(sB, 1.0f, bias, out);      // final
}

// round 5
// speedup vs baseline: 1.1206x; 1.1206x over previous
#include <cuda_runtime.h>
#include <cuda_fp16.h>

#define BB   256
#define NN   1152
#define OO   10
#define JJ   160              // floats per (b,n): j = o*16+k
#define WW   80               // half2 words per (b,n)
#define EPSF 1e-7f
#define NPART 16
#define NPERW 9               // 1152 / (NPART*8 warps)

// ---- scratch (static device globals; no allocation) ----
__device__ __half2 g_uh[(size_t)BB * NN * WW];     // 94.5 MB, [b][n][w]
__device__ float   g_part[144 * BB * JJ];          // 23.6 MB uhat partials
__device__ float   g_s0[BB * JJ];
__device__ float   g_sA[BB * JJ];
__device__ float   g_sB[BB * JJ];
__device__ float   g_b1[(size_t)BB * NN * OO];     // 11.8 MB logits after iter-0

// ---------------------------------------------------------------------------
__global__ void k_zero() {
    int i = blockIdx.x * blockDim.x + threadIdx.x;
    if (i < BB * JJ) { g_s0[i] = 0.f; g_sA[i] = 0.f; g_sB[i] = 0.f; }
}

// ---------------------------------------------------------------------------
// u_hat (fp32 compute, fp16 store) + iter-0 partials.  (round-3 proven form)
__global__ void __launch_bounds__(160) k_uhat(const float* __restrict__ x,
                                              const float* __restrict__ w) {
    const int j  = threadIdx.x;
    const int n0 = blockIdx.x * 8;
    const int b0 = blockIdx.y * 32;

    __shared__ __align__(16) float x_sm[32 * 64];
    for (int idx = j; idx < 32 * 64; idx += 160) {
        int bb = idx >> 6, q = idx & 63;
        x_sm[idx] = x[(size_t)(b0 + bb) * (NN * 8) + n0 * 8 + q];
    }

    float Wr[8][8];
    {
        const int wb = (j >> 4) * 128 + (j & 15);   // o*128 + k
        #pragma unroll
        for (int n = 0; n < 8; n++)
            #pragma unroll
            for (int i = 0; i < 8; i++)
                Wr[n][i] = w[(size_t)(n0 + n) * 1280 + wb + i * 16];
    }
    __syncthreads();

    __half* gh = (__half*)g_uh;
    for (int bb = 0; bb < 32; bb++) {
        float acc = 0.f;
        __half* outp = &gh[((size_t)(b0 + bb) * NN + n0) * JJ + j];
        #pragma unroll
        for (int n = 0; n < 8; n++) {
            const float4* xv = reinterpret_cast<const float4*>(&x_sm[bb * 64 + n * 8]);
            float4 xa = xv[0], xb = xv[1];
            float u = Wr[n][0] * xa.x + Wr[n][1] * xa.y + Wr[n][2] * xa.z + Wr[n][3] * xa.w
                    + Wr[n][4] * xb.x + Wr[n][5] * xb.y + Wr[n][6] * xb.z + Wr[n][7] * xb.w;
            outp[n * JJ] = __float2half(u);
            acc += u;
        }
        g_part[((size_t)blockIdx.x * BB + (b0 + bb)) * JJ + j] = acc;
    }
}

// ---------------------------------------------------------------------------
__global__ void k_red0() {
    const int b = blockIdx.x, j = threadIdx.x;
    const int nb0 = blockIdx.y * 18;
    float s = 0.f;
    #pragma unroll 6
    for (int nb = nb0; nb < nb0 + 18; nb++)
        s += g_part[((size_t)nb * BB + b) * JJ + j];
    atomicAdd(&g_s0[b * JJ + j], s);
}

// ---------------------------------------------------------------------------
__global__ void k_squash(const float* __restrict__ sbuf, float scale,
                         const float* __restrict__ bias, float* __restrict__ dst) {
    const int b = blockIdx.x, j = threadIdx.x;
    float s = scale * sbuf[b * JJ + j] + bias[j];
    float d = s * s;
    #pragma unroll
    for (int msk = 1; msk < 16; msk <<= 1)
        d += __shfl_xor_sync(0xffffffffu, d, msk, 16);
    dst[b * JJ + j] = s * (d / ((1.f + d) * sqrtf(d + EPSF)));
}

// ---------------------------------------------------------------------------
// Routing iteration with fused v-squash and ILP-3 mainloop.
// grid (256 b, NPART), block 256.  v recomputed per block from sin.
// Lanes 0..19 own 16B of the 320B u-row: lane l -> half2 words 4l..4l+3, o=l>>1.
template <int LAST>
__global__ void __launch_bounds__(256) k_route(const float* __restrict__ sin,
                                               float sscale,
                                               const float* __restrict__ bias,
                                               float* __restrict__ sout) {
    const int b   = blockIdx.x;
    const int tid = threadIdx.x;
    const int wp  = tid >> 5, l = tid & 31;
    const unsigned FULL = 0xffffffffu;
    const bool act = (l < 20);

    __shared__ __align__(16) float v_sm[JJ];
    if (tid < JJ) {
        float s = sscale * sin[b * JJ + tid] + bias[tid];
        float d = s * s;
        #pragma unroll
        for (int msk = 1; msk < 16; msk <<= 1)
            d += __shfl_xor_sync(FULL, d, msk, 16);
        v_sm[tid] = s * (d / ((1.f + d) * sqrtf(d + EPSF)));
    }
    __syncthreads();

    float4 va = make_float4(0.f, 0.f, 0.f, 0.f), vb = va;
    if (act) {
        const float4* vp = (const float4*)v_sm;
        va = vp[2 * l]; vb = vp[2 * l + 1];
    }
    float4 sa = make_float4(0.f, 0.f, 0.f, 0.f), sb = sa;

    const __half2* up = g_uh + (size_t)b * NN * WW;
    const int nbeg = (blockIdx.y * 8 + wp) * NPERW;

    for (int g = 0; g < 3; g++) {
        const int n0g = nbeg + g * 3;
        float4 uw[3];
        float2 u0[3], u1[3], u2[3], u3[3];
        float p[3], bn[3], e[3], tot[3], cf[3];

        #pragma unroll
        for (int r = 0; r < 3; r++) {
            uw[r] = make_float4(0.f, 0.f, 0.f, 0.f);
            if (act) uw[r] = ((const float4*)(up + (size_t)(n0g + r) * WW))[l];
        }
        #pragma unroll
        for (int r = 0; r < 3; r++) {
            const __half2* hp = (const __half2*)&uw[r];
            u0[r] = __half22float2(hp[0]); u1[r] = __half22float2(hp[1]);
            u2[r] = __half22float2(hp[2]); u3[r] = __half22float2(hp[3]);
            p[r] = u0[r].x * va.x + u0[r].y * va.y + u1[r].x * va.z + u1[r].y * va.w
                 + u2[r].x * vb.x + u2[r].y * vb.y + u3[r].x * vb.z + u3[r].y * vb.w;
        }
        #pragma unroll
        for (int r = 0; r < 3; r++) p[r] += __shfl_xor_sync(FULL, p[r], 1);
        #pragma unroll
        for (int r = 0; r < 3; r++) bn[r] = __shfl_sync(FULL, p[r], (l & 15) << 1);

        if (LAST) {
            #pragma unroll
            for (int r = 0; r < 3; r++)
                if (l < 10) bn[r] += g_b1[((size_t)b * NN + n0g + r) * OO + l];
        } else {
            #pragma unroll
            for (int r = 0; r < 3; r++)
                if (l < 10) g_b1[((size_t)b * NN + n0g + r) * OO + l] = bn[r];
        }
        #pragma unroll
        for (int r = 0; r < 3; r++) e[r] = (l < 10) ? __expf(bn[r]) : 0.f;
        #pragma unroll
        for (int r = 0; r < 3; r++) tot[r] = e[r];
        #pragma unroll
        for (int msk = 1; msk < 16; msk <<= 1) {
            #pragma unroll
            for (int r = 0; r < 3; r++)
                tot[r] += __shfl_xor_sync(FULL, tot[r], msk, 16);
        }
        #pragma unroll
        for (int r = 0; r < 3; r++) cf[r] = __fdividef(e[r], tot[r]);
        #pragma unroll
        for (int r = 0; r < 3; r++) {
            float c = __shfl_sync(FULL, cf[r], l >> 1);
            sa.x += c * u0[r].x; sa.y += c * u0[r].y;
            sa.z += c * u1[r].x; sa.w += c * u1[r].y;
            sb.x += c * u2[r].x; sb.y += c * u2[r].y;
            sb.z += c * u3[r].x; sb.w += c * u3[r].y;
        }
    }

    __shared__ float ssm[8][JJ];
    if (act) {
        float4* sp = (float4*)&ssm[wp][8 * l];
        sp[0] = sa; sp[1] = sb;
    }
    __syncthreads();

    if (tid < JJ) {
        float s = 0.f;
        #pragma unroll
        for (int w8 = 0; w8 < 8; w8++) s += ssm[w8][tid];
        atomicAdd(&sout[b * JJ + tid], s);
    }
}

// ---------------------------------------------------------------------------
extern "C" void kernel_launch(void* const* d_in, const int* in_sizes, int n_in,
                              void* d_out, int out_size) {
    const float* x    = (const float*)d_in[0];
    const float* w    = (const float*)d_in[1];
    const float* bias = (const float*)d_in[2];
    float* out = (float*)d_out;

    float* s0; cudaGetSymbolAddress((void**)&s0, g_s0);
    float* sA; cudaGetSymbolAddress((void**)&sA, g_sA);
    float* sB; cudaGetSymbolAddress((void**)&sB, g_sB);

    k_zero<<<40, 1024>>>();
    k_uhat<<<dim3(144, 8), 160>>>(x, w);
    k_red0<<<dim3(256, 8), 160>>>();
    k_route<0><<<dim3(256, NPART), 256>>>(s0, 0.1f, bias, sA);  // v0 in-block; b1 store
    k_route<1><<<dim3(256, NPART), 256>>>(sA, 1.0f, bias, sB);  // v1 in-block; b1 load
    k_squash<<<256, 160>>>(sB, 1.0f, bias, out);                // final
}

// round 7
// speedup vs baseline: 1.2293x; 1.0970x over previous
#include <cuda_runtime.h>
#include <cuda_fp16.h>

#define BB   256
#define NN   1152
#define OO   10
#define JJ   160              // floats per (b,n): j = o*16+k
#define WW   80               // half2 words per (b,n)
#define EPSF 1e-7f
#define NPART 32
#define NPERW 9               // 1152 / (NPART*4 warps)

typedef unsigned long long ull;

// ---- scratch (static device globals; no allocation) ----
__device__ __half2 g_uh[(size_t)BB * NN * WW];     // 94.5 MB, [b][n][w]
__device__ float   g_part[144 * BB * JJ];          // 23.6 MB uhat partials
__device__ float   g_s0[BB * JJ];
__device__ float   g_sA[BB * JJ];
__device__ float   g_sB[BB * JJ];
__device__ float   g_b1[(size_t)BB * NN * OO];     // 11.8 MB logits after iter-0

// ---- packed f32x2 helpers (Blackwell PTX-only FFMA2 path) ----
__device__ __forceinline__ ull fma2(ull a, ull b, ull c) {
    ull d; asm("fma.rn.f32x2 %0, %1, %2, %3;" : "=l"(d) : "l"(a), "l"(b), "l"(c));
    return d;
}
__device__ __forceinline__ ull add2(ull a, ull b) {
    ull d; asm("add.rn.f32x2 %0, %1, %2;" : "=l"(d) : "l"(a), "l"(b));
    return d;
}
__device__ __forceinline__ ull pack2(float lo, float hi) {
    ull d; asm("mov.b64 %0, {%1, %2};" : "=l"(d) : "f"(lo), "f"(hi));
    return d;
}
__device__ __forceinline__ float2 unpack2(ull v) {
    float lo, hi; asm("mov.b64 {%0, %1}, %2;" : "=f"(lo), "=f"(hi) : "l"(v));
    return make_float2(lo, hi);
}

// ---------------------------------------------------------------------------
__global__ void k_zero() {
    int i = blockIdx.x * blockDim.x + threadIdx.x;
    if (i < BB * JJ) { g_s0[i] = 0.f; g_sA[i] = 0.f; g_sB[i] = 0.f; }
}

// ---------------------------------------------------------------------------
// u_hat via packed f32x2 FMA over n-pairs.  grid (144, 8), block 160 (thread=j).
// x staged TRANSPOSED in smem: x_sm[bb][i*8+n] so (x[n][i],x[n+1][i]) = one LDS.64.
__global__ void __launch_bounds__(160) k_uhat(const float* __restrict__ x,
                                              const float* __restrict__ w) {
    const int j  = threadIdx.x;
    const int n0 = blockIdx.x * 8;
    const int b0 = blockIdx.y * 32;

    __shared__ __align__(16) float x_sm[32 * 64];   // [bb][i*8+n]
    for (int idx = j; idx < 32 * 64; idx += 160) {
        int bb = idx >> 6, q = idx & 63;            // q = n*8+i in source order
        int n = q >> 3, i = q & 7;
        x_sm[bb * 64 + i * 8 + n] = x[(size_t)(b0 + bb) * (NN * 8) + (n0 + n) * 8 + i];
    }

    ull Wp[4][8];                                    // (W[n], W[n+1]) pairs
    {
        const int wb = (j >> 4) * 128 + (j & 15);    // o*128 + k
        #pragma unroll
        for (int p = 0; p < 4; p++)
            #pragma unroll
            for (int i = 0; i < 8; i++) {
                float a = w[(size_t)(n0 + 2 * p)     * 1280 + wb + i * 16];
                float b = w[(size_t)(n0 + 2 * p + 1) * 1280 + wb + i * 16];
                Wp[p][i] = pack2(a, b);
            }
    }
    __syncthreads();

    __half* gh = (__half*)g_uh;
    const ull z2 = pack2(0.f, 0.f);
    for (int bb = 0; bb < 32; bb++) {
        ull s2 = z2;
        __half* outp = &gh[((size_t)(b0 + bb) * NN + n0) * JJ + j];
        const ull* xrow = (const ull*)&x_sm[bb * 64];
        #pragma unroll
        for (int p = 0; p < 4; p++) {
            ull acc = z2;
            #pragma unroll
            for (int i = 0; i < 8; i++)
                acc = fma2(Wp[p][i], xrow[i * 4 + p], acc);   // broadcast LDS.64
            s2 = add2(s2, acc);
            float2 u = unpack2(acc);
            outp[(2 * p)     * JJ] = __float2half(u.x);
            outp[(2 * p + 1) * JJ] = __float2half(u.y);
        }
        float2 sf = unpack2(s2);
        g_part[((size_t)blockIdx.x * BB + (b0 + bb)) * JJ + j] = sf.x + sf.y;
    }
}

// ---------------------------------------------------------------------------
__global__ void k_red0() {
    const int b = blockIdx.x, j = threadIdx.x;
    const int nb0 = blockIdx.y * 18;
    float s = 0.f;
    #pragma unroll 6
    for (int nb = nb0; nb < nb0 + 18; nb++)
        s += g_part[((size_t)nb * BB + b) * JJ + j];
    atomicAdd(&g_s0[b * JJ + j], s);
}

// ---------------------------------------------------------------------------
__global__ void k_squash(const float* __restrict__ sbuf, float scale,
                         const float* __restrict__ bias, float* __restrict__ dst) {
    const int b = blockIdx.x, j = threadIdx.x;
    float s = scale * sbuf[b * JJ + j] + bias[j];
    float d = s * s;
    #pragma unroll
    for (int msk = 1; msk < 16; msk <<= 1)
        d += __shfl_xor_sync(0xffffffffu, d, msk, 16);
    dst[b * JJ + j] = s * (d / ((1.f + d) * sqrtf(d + EPSF)));
}

// ---------------------------------------------------------------------------
// Routing iteration: fused v-squash, batched MLP-9 loads, pair-local softmax.
// grid (256 b, NPART), block 128 (4 warps, NPERW n each).
// Lanes 0..19 own 16B of the 320B u-row: lane l -> half2 words 4l..4l+3, o=l>>1.
template <int LAST>
__global__ void __launch_bounds__(128) k_route(const float* __restrict__ sin,
                                               float sscale,
                                               const float* __restrict__ bias,
                                               float* __restrict__ sout) {
    const int b   = blockIdx.x;
    const int tid = threadIdx.x;
    const int wp  = tid >> 5, l = tid & 31;
    const unsigned FULL = 0xffffffffu;
    const bool act = (l < 20);

    __shared__ __align__(16) float v_sm[JJ];
    {   // phase 1: j = tid (capsules 0..7); phase 2: warp0 does j = 128+tid (o=8,9)
        float s = sscale * sin[b * JJ + tid] + bias[tid];
        float d = s * s;
        #pragma unroll
        for (int msk = 1; msk < 16; msk <<= 1)
            d += __shfl_xor_sync(FULL, d, msk, 16);
        v_sm[tid] = s * (d / ((1.f + d) * sqrtf(d + EPSF)));
        if (tid < 32) {
            int j2 = 128 + tid;
            float s2 = sscale * sin[b * JJ + j2] + bias[j2];
            float d2 = s2 * s2;
            #pragma unroll
            for (int msk = 1; msk < 16; msk <<= 1)
                d2 += __shfl_xor_sync(FULL, d2, msk, 16);
            v_sm[j2] = s2 * (d2 / ((1.f + d2) * sqrtf(d2 + EPSF)));
        }
    }
    __syncthreads();

    float4 va = make_float4(0.f, 0.f, 0.f, 0.f), vb = va;
    if (act) {
        const float4* vp = (const float4*)v_sm;
        va = vp[2 * l]; vb = vp[2 * l + 1];
    }
    float4 sa = make_float4(0.f, 0.f, 0.f, 0.f), sb = sa;

    const __half2* up = g_uh + (size_t)b * NN * WW;
    const int nbeg = (blockIdx.y * 4 + wp) * NPERW;
    const int o = l >> 1;

    // batch all 9 row-loads (MLP 9)
    float4 uw[NPERW];
    #pragma unroll
    for (int r = 0; r < NPERW; r++) {
        uw[r] = make_float4(0.f, 0.f, 0.f, 0.f);
        if (act) uw[r] = ((const float4*)(up + (size_t)(nbeg + r) * WW))[l];
    }
    float bl[NPERW];
    if (LAST) {
        #pragma unroll
        for (int r = 0; r < NPERW; r++)
            bl[r] = act ? g_b1[((size_t)b * NN + nbeg + r) * OO + o] : 0.f;
    }

    #pragma unroll
    for (int r = 0; r < NPERW; r++) {
        const __half2* hp = (const __half2*)&uw[r];
        float2 u0 = __half22float2(hp[0]), u1 = __half22float2(hp[1]);
        float2 u2 = __half22float2(hp[2]), u3 = __half22float2(hp[3]);

        float p = u0.x * va.x + u0.y * va.y + u1.x * va.z + u1.y * va.w
                + u2.x * vb.x + u2.y * vb.y + u3.x * vb.z + u3.y * vb.w;
        p += __shfl_xor_sync(FULL, p, 1);          // both pair lanes hold dot[o]

        float bn = p;
        if (LAST) bn += bl[r];
        else if (act && !(l & 1))
            g_b1[((size_t)b * NN + nbeg + r) * OO + o] = bn;

        float e = act ? __expf(bn) : 0.f;          // duplicated per pair
        float tot = e;                             // Σ over 32 lanes = 2·Σ_o e
        #pragma unroll
        for (int msk = 1; msk < 32; msk <<= 1)
            tot += __shfl_xor_sync(FULL, tot, msk);
        float c = __fdividef(e + e, tot);          // c = e / Σ_o e, already local

        sa.x += c * u0.x; sa.y += c * u0.y; sa.z += c * u1.x; sa.w += c * u1.y;
        sb.x += c * u2.x; sb.y += c * u2.y; sb.z += c * u3.x; sb.w += c * u3.y;
    }

    __shared__ float ssm[4][JJ];
    if (act) {
        float4* sp = (float4*)&ssm[wp][8 * l];
        sp[0] = sa; sp[1] = sb;
    }
    __syncthreads();

    for (int jj = tid; jj < JJ; jj += 128) {
        float s = ssm[0][jj] + ssm[1][jj] + ssm[2][jj] + ssm[3][jj];
        atomicAdd(&sout[b * JJ + jj], s);
    }
}

// ---------------------------------------------------------------------------
extern "C" void kernel_launch(void* const* d_in, const int* in_sizes, int n_in,
                              void* d_out, int out_size) {
    const float* x    = (const float*)d_in[0];
    const float* w    = (const float*)d_in[1];
    const float* bias = (const float*)d_in[2];
    float* out = (float*)d_out;

    float* s0; cudaGetSymbolAddress((void**)&s0, g_s0);
    float* sA; cudaGetSymbolAddress((void**)&sA, g_sA);
    float* sB; cudaGetSymbolAddress((void**)&sB, g_sB);

    k_zero<<<40, 1024>>>();
    k_uhat<<<dim3(144, 8), 160>>>(x, w);
    k_red0<<<dim3(256, 8), 160>>>();
    k_route<0><<<dim3(256, NPART), 128>>>(s0, 0.1f, bias, sA);  // v0 fused; b1 store
    k_route<1><<<dim3(256, NPART), 128>>>(sA, 1.0f, bias, sB);  // v1 fused; b1 load
    k_squash<<<256, 160>>>(sB, 1.0f, bias, out);                // final
}

// round 8
// speedup vs baseline: 1.3368x; 1.0874x over previous
#include <cuda_runtime.h>
#include <cuda_fp16.h>

#define BB   256
#define NN   1152
#define OO   10
#define JJ   160              // floats per (b,n): j = o*16+k
#define WW   80               // half2 words per (b,n)
#define EPSF 1e-7f
#define NPART 16
#define NPERW 18              // n per warp: 1152/(NPART*4)

typedef unsigned long long ull;

// ---- scratch (static device globals; no allocation) ----
__device__ __half2 g_uh[(size_t)BB * NN * WW];     // 94.5 MB, [b][n][w]
__device__ float   g_part[144 * BB * JJ];          // 23.6 MB uhat partials
__device__ float   g_s0[BB * JJ];
__device__ float   g_sA[BB * JJ];
__device__ float   g_sB[BB * JJ];

// ---- packed f32x2 helpers ----
__device__ __forceinline__ ull fma2(ull a, ull b, ull c) {
    ull d; asm("fma.rn.f32x2 %0, %1, %2, %3;" : "=l"(d) : "l"(a), "l"(b), "l"(c));
    return d;
}
__device__ __forceinline__ ull add2(ull a, ull b) {
    ull d; asm("add.rn.f32x2 %0, %1, %2;" : "=l"(d) : "l"(a), "l"(b));
    return d;
}
__device__ __forceinline__ ull pack2(float lo, float hi) {
    ull d; asm("mov.b64 %0, {%1, %2};" : "=l"(d) : "f"(lo), "f"(hi));
    return d;
}
__device__ __forceinline__ float2 unpack2(ull v) {
    float lo, hi; asm("mov.b64 {%0, %1}, %2;" : "=f"(lo), "=f"(hi) : "l"(v));
    return make_float2(lo, hi);
}

// ---------------------------------------------------------------------------
__global__ void k_zero() {
    int i = blockIdx.x * blockDim.x + threadIdx.x;
    if (i < BB * JJ) { g_s0[i] = 0.f; g_sA[i] = 0.f; g_sB[i] = 0.f; }
}

// ---------------------------------------------------------------------------
// u_hat via packed f32x2 FMA over n-pairs (proven round-7 form).
__global__ void __launch_bounds__(160) k_uhat(const float* __restrict__ x,
                                              const float* __restrict__ w) {
    const int j  = threadIdx.x;
    const int n0 = blockIdx.x * 8;
    const int b0 = blockIdx.y * 32;

    __shared__ __align__(16) float x_sm[32 * 64];   // [bb][i*8+n]
    for (int idx = j; idx < 32 * 64; idx += 160) {
        int bb = idx >> 6, q = idx & 63;
        int n = q >> 3, i = q & 7;
        x_sm[bb * 64 + i * 8 + n] = x[(size_t)(b0 + bb) * (NN * 8) + (n0 + n) * 8 + i];
    }

    ull Wp[4][8];
    {
        const int wb = (j >> 4) * 128 + (j & 15);
        #pragma unroll
        for (int p = 0; p < 4; p++)
            #pragma unroll
            for (int i = 0; i < 8; i++) {
                float a = w[(size_t)(n0 + 2 * p)     * 1280 + wb + i * 16];
                float b = w[(size_t)(n0 + 2 * p + 1) * 1280 + wb + i * 16];
                Wp[p][i] = pack2(a, b);
            }
    }
    __syncthreads();

    __half* gh = (__half*)g_uh;
    const ull z2 = pack2(0.f, 0.f);
    for (int bb = 0; bb < 32; bb++) {
        ull s2 = z2;
        __half* outp = &gh[((size_t)(b0 + bb) * NN + n0) * JJ + j];
        const ull* xrow = (const ull*)&x_sm[bb * 64];
        #pragma unroll
        for (int p = 0; p < 4; p++) {
            ull acc = z2;
            #pragma unroll
            for (int i = 0; i < 8; i++)
                acc = fma2(Wp[p][i], xrow[i * 4 + p], acc);
            s2 = add2(s2, acc);
            float2 u = unpack2(acc);
            outp[(2 * p)     * JJ] = __float2half(u.x);
            outp[(2 * p + 1) * JJ] = __float2half(u.y);
        }
        float2 sf = unpack2(s2);
        g_part[((size_t)blockIdx.x * BB + (b0 + bb)) * JJ + j] = sf.x + sf.y;
    }
}

// ---------------------------------------------------------------------------
__global__ void k_red0() {
    const int b = blockIdx.x, j = threadIdx.x;
    const int nb0 = blockIdx.y * 18;
    float s = 0.f;
    #pragma unroll 6
    for (int nb = nb0; nb < nb0 + 18; nb++)
        s += g_part[((size_t)nb * BB + b) * JJ + j];
    atomicAdd(&g_s0[b * JJ + j], s);
}

// ---------------------------------------------------------------------------
__global__ void k_squash(const float* __restrict__ sbuf, float scale,
                         const float* __restrict__ bias, float* __restrict__ dst) {
    const int b = blockIdx.x, j = threadIdx.x;
    float s = scale * sbuf[b * JJ + j] + bias[j];
    float d = s * s;
    #pragma unroll
    for (int msk = 1; msk < 16; msk <<= 1)
        d += __shfl_xor_sync(0xffffffffu, d, msk, 16);
    dst[b * JJ + j] = s * (d / ((1.f + d) * sqrtf(d + EPSF)));
}

// ---------------------------------------------------------------------------
// squash helper for in-block v computation (width-16 butterfly over j groups)
__device__ __forceinline__ float squash1(float s) {
    float d = s * s;
    #pragma unroll
    for (int msk = 1; msk < 16; msk <<= 1)
        d += __shfl_xor_sync(0xffffffffu, d, msk, 16);
    return s * (d / ((1.f + d) * sqrtf(d + EPSF)));
}

// ---------------------------------------------------------------------------
// Routing iteration, 2-n-per-warp-step layout, b1-free (logits = dot(u, vsum)).
// ITER=1: vsum = v0 = squash(0.1*s0+bias).  ITER=2: vsum = v0 + v1, v1 = squash(sA+bias).
// grid (256 b, NPART), block 128 (4 warps, NPERW=18 n = 9 pairs each).
// Lane l<20: parity = l&1 (n vs n+1), o = l>>1; lane-local 16-k dot, 4-shfl softmax.
template <int ITER>
__global__ void __launch_bounds__(128) k_route(const float* __restrict__ s0in,
                                               const float* __restrict__ sAin,
                                               const float* __restrict__ bias,
                                               float* __restrict__ sout) {
    const int b   = blockIdx.x;
    const int tid = threadIdx.x;
    const int wp  = tid >> 5, l = tid & 31;
    const unsigned FULL = 0xffffffffu;
    const bool act = (l < 20);

    __shared__ __align__(16) float vsum_sm[JJ];
    {
        float v = squash1(0.1f * s0in[b * JJ + tid] + bias[tid]);
        if (ITER == 2) v += squash1(sAin[b * JJ + tid] + bias[tid]);
        vsum_sm[tid] = v;
        if (tid < 32) {
            int j2 = 128 + tid;
            float v2 = squash1(0.1f * s0in[b * JJ + j2] + bias[j2]);
            if (ITER == 2) v2 += squash1(sAin[b * JJ + j2] + bias[j2]);
            vsum_sm[j2] = v2;
        }
    }
    __syncthreads();

    // per-lane v slice: vreg[k] = vsum[o*16+k]
    float vreg[16];
    {
        const int o = l >> 1;
        const float4* vp = (const float4*)&vsum_sm[(act ? o : 0) * 16];
        #pragma unroll
        for (int q = 0; q < 4; q++) {
            float4 t = vp[q];
            vreg[4 * q] = t.x; vreg[4 * q + 1] = t.y;
            vreg[4 * q + 2] = t.z; vreg[4 * q + 3] = t.w;
        }
    }

    float sacc[16];
    #pragma unroll
    for (int k = 0; k < 16; k++) sacc[k] = 0.f;

    const int nbeg = (blockIdx.y * 4 + wp) * NPERW;
    const char* ub = (const char*)g_uh + ((size_t)b * NN + nbeg) * 320
                   + (l & 1) * 320 + (l >> 1) * 32;

    for (int g = 0; g < 3; g++) {                    // 3 groups of 3 pairs
        float4 A[3], Bq[3];
        #pragma unroll
        for (int p = 0; p < 3; p++) {
            const char* ap = ub + (g * 3 + p) * 640;
            A[p]  = act ? *(const float4*)ap        : make_float4(0.f, 0.f, 0.f, 0.f);
            Bq[p] = act ? *(const float4*)(ap + 16) : make_float4(0.f, 0.f, 0.f, 0.f);
        }
        #pragma unroll
        for (int p = 0; p < 3; p++) {
            const __half2* h2a = (const __half2*)&A[p];
            const __half2* h2b = (const __half2*)&Bq[p];
            // dot (lane-local)
            float acc = 0.f;
            #pragma unroll
            for (int i = 0; i < 4; i++) {
                float2 t = __half22float2(h2a[i]);
                acc = fmaf(t.x, vreg[2 * i], fmaf(t.y, vreg[2 * i + 1], acc));
            }
            #pragma unroll
            for (int i = 0; i < 4; i++) {
                float2 t = __half22float2(h2b[i]);
                acc = fmaf(t.x, vreg[8 + 2 * i], fmaf(t.y, vreg[8 + 2 * i + 1], acc));
            }
            float e = act ? __expf(acc) : 0.f;
            float tot = e;                           // sum over same-parity lanes
            tot += __shfl_xor_sync(FULL, tot, 2);
            tot += __shfl_xor_sync(FULL, tot, 4);
            tot += __shfl_xor_sync(FULL, tot, 8);
            tot += __shfl_xor_sync(FULL, tot, 16);
            float c = __fdividef(e, tot);
            // s accumulation (lane-local)
            #pragma unroll
            for (int i = 0; i < 4; i++) {
                float2 t = __half22float2(h2a[i]);
                sacc[2 * i]     = fmaf(c, t.x, sacc[2 * i]);
                sacc[2 * i + 1] = fmaf(c, t.y, sacc[2 * i + 1]);
            }
            #pragma unroll
            for (int i = 0; i < 4; i++) {
                float2 t = __half22float2(h2b[i]);
                sacc[8 + 2 * i]     = fmaf(c, t.x, sacc[8 + 2 * i]);
                sacc[8 + 2 * i + 1] = fmaf(c, t.y, sacc[8 + 2 * i + 1]);
            }
        }
    }

    // merge: [4 warps][2 parities][160]
    __shared__ __align__(16) float ssm[4][2][JJ];
    if (act) {
        float4* sp = (float4*)&ssm[wp][l & 1][(l >> 1) * 16];
        #pragma unroll
        for (int q = 0; q < 4; q++)
            sp[q] = make_float4(sacc[4 * q], sacc[4 * q + 1],
                                sacc[4 * q + 2], sacc[4 * q + 3]);
    }
    __syncthreads();

    for (int jj = tid; jj < JJ; jj += 128) {
        float s = 0.f;
        #pragma unroll
        for (int w4 = 0; w4 < 4; w4++)
            s += ssm[w4][0][jj] + ssm[w4][1][jj];
        atomicAdd(&sout[b * JJ + jj], s);
    }
}

// ---------------------------------------------------------------------------
extern "C" void kernel_launch(void* const* d_in, const int* in_sizes, int n_in,
                              void* d_out, int out_size) {
    const float* x    = (const float*)d_in[0];
    const float* w    = (const float*)d_in[1];
    const float* bias = (const float*)d_in[2];
    float* out = (float*)d_out;

    float* s0; cudaGetSymbolAddress((void**)&s0, g_s0);
    float* sA; cudaGetSymbolAddress((void**)&sA, g_sA);
    float* sB; cudaGetSymbolAddress((void**)&sB, g_sB);

    k_zero<<<40, 1024>>>();
    k_uhat<<<dim3(144, 8), 160>>>(x, w);
    k_red0<<<dim3(256, 8), 160>>>();
    k_route<1><<<dim3(256, NPART), 128>>>(s0, nullptr, bias, sA);  // iter 1
    k_route<2><<<dim3(256, NPART), 128>>>(s0, sA, bias, sB);       // iter 2
    k_squash<<<256, 160>>>(sB, 1.0f, bias, out);                   // final
}